// round 5
// baseline (speedup 1.0000x reference)
#include <cuda_runtime.h>

#define KDIM  256
#define NF    64
#define N1R   8192
#define KH    5
#define BM    32
#define BK    32
#define NCHUNK (KDIM / BK)

// ---------------------------------------------------------------------------
// Fused: out = G @ x @ W + 5*bias, where G rows are 5 ones at qq[5i..5i+4]
// (floor(softmax/1000) == 0 identically, so e == G exactly.)
// One CTA = 32 output rows x all 64 cols. 128 threads, 4x4 microtile.
// Gather-sum of x happens in the global->smem stage; double-buffered smem
// with register prefetch hides L2 latency behind FFMA work.
// ---------------------------------------------------------------------------
__global__ __launch_bounds__(128) void fused_kernel(const float* __restrict__ x,
                                                    const int* __restrict__ qq,
                                                    const float* __restrict__ w,
                                                    const float* __restrict__ bias,
                                                    float* __restrict__ out) {
    __shared__ float sst[2][BK][36];   // transposed s tile: [k][row], pad 36 (144B rows keep 16B align)
    __shared__ float ws[2][BK][NF];    // w tile
    __shared__ int   qs[BM * KH];      // 160 indices for this CTA

    const int tid = threadIdx.x;
    const int r0  = blockIdx.x * BM;
    const int rg  = tid >> 4;          // 0..7  -> rows rg*4 .. rg*4+3
    const int cg  = tid & 15;          // 0..15 -> cols cg*4 .. cg*4+3

    // 160 entries with 128 threads -> strided loop
    for (int t = tid; t < BM * KH; t += 128) qs[t] = qq[r0 * KH + t];
    __syncthreads();

    const float4* x4 = (const float4*)x;   // x row stride = 256 floats = 64 float4  (R4 BUG: was *16)
    const float4* w4 = (const float4*)w;   // w row stride = 64 floats = 16 float4

    // decomposition for the load stages
    const int lrow0 = tid >> 3;            // 0..15  (j adds 16)
    const int lc4   = tid & 7;             // x float4 col within chunk
    const int wkk0  = tid >> 4;            // 0..7   (j adds 8)
    const int wc4   = tid & 15;            // w float4 col

    float4 xa[2][KH];                      // gather prefetch
    float4 wr[4];                          // w prefetch
    float  acc[4][4] = {};

#define ISSUE_LOADS(k0)                                                        \
    {                                                                          \
        _Pragma("unroll")                                                      \
        for (int j = 0; j < 2; j++) {                                          \
            int row = lrow0 + j * 16;                                          \
            const float4* xp = x4 + ((k0) >> 2) + lc4;                         \
            _Pragma("unroll")                                                  \
            for (int t = 0; t < KH; t++)                                       \
                xa[j][t] = xp[(size_t)qs[row * KH + t] * 64];                  \
        }                                                                      \
        _Pragma("unroll")                                                      \
        for (int j = 0; j < 4; j++) {                                          \
            int kk = wkk0 + j * 8;                                             \
            wr[j] = w4[(size_t)((k0) + kk) * 16 + wc4];                        \
        }                                                                      \
    }

#define STORE_STAGE(b)                                                         \
    {                                                                          \
        _Pragma("unroll")                                                      \
        for (int j = 0; j < 2; j++) {                                          \
            int row = lrow0 + j * 16;                                          \
            float4 s;                                                          \
            s.x = xa[j][0].x + xa[j][1].x + xa[j][2].x + xa[j][3].x + xa[j][4].x; \
            s.y = xa[j][0].y + xa[j][1].y + xa[j][2].y + xa[j][3].y + xa[j][4].y; \
            s.z = xa[j][0].z + xa[j][1].z + xa[j][2].z + xa[j][3].z + xa[j][4].z; \
            s.w = xa[j][0].w + xa[j][1].w + xa[j][2].w + xa[j][3].w + xa[j][4].w; \
            sst[b][lc4 * 4 + 0][row] = s.x;                                    \
            sst[b][lc4 * 4 + 1][row] = s.y;                                    \
            sst[b][lc4 * 4 + 2][row] = s.z;                                    \
            sst[b][lc4 * 4 + 3][row] = s.w;                                    \
        }                                                                      \
        _Pragma("unroll")                                                      \
        for (int j = 0; j < 4; j++) {                                          \
            int kk = wkk0 + j * 8;                                             \
            *(float4*)&ws[b][kk][wc4 * 4] = wr[j];                             \
        }                                                                      \
    }

    // ---- pipeline ----
    ISSUE_LOADS(0);
    STORE_STAGE(0);
    __syncthreads();

    #pragma unroll 1
    for (int c = 0; c < NCHUNK; c++) {
        const int b = c & 1;
        if (c < NCHUNK - 1) ISSUE_LOADS((c + 1) * BK);

        #pragma unroll
        for (int kk = 0; kk < BK; kk++) {
            float4 sv = *(const float4*)&sst[b][kk][rg * 4];
            float4 wv = *(const float4*)&ws[b][kk][cg * 4];
            acc[0][0] += sv.x * wv.x; acc[0][1] += sv.x * wv.y;
            acc[0][2] += sv.x * wv.z; acc[0][3] += sv.x * wv.w;
            acc[1][0] += sv.y * wv.x; acc[1][1] += sv.y * wv.y;
            acc[1][2] += sv.y * wv.z; acc[1][3] += sv.y * wv.w;
            acc[2][0] += sv.z * wv.x; acc[2][1] += sv.z * wv.y;
            acc[2][2] += sv.z * wv.z; acc[2][3] += sv.z * wv.w;
            acc[3][0] += sv.w * wv.x; acc[3][1] += sv.w * wv.y;
            acc[3][2] += sv.w * wv.z; acc[3][3] += sv.w * wv.w;
        }

        if (c < NCHUNK - 1) STORE_STAGE(b ^ 1);
        __syncthreads();
    }

    // ---- epilogue: + 5*bias, store ----
    float4 bv = ((const float4*)bias)[cg];
    float4* out4 = (float4*)out;
    #pragma unroll
    for (int m = 0; m < 4; m++) {
        int row = r0 + rg * 4 + m;
        float4 o;
        o.x = acc[m][0] + 5.0f * bv.x;
        o.y = acc[m][1] + 5.0f * bv.y;
        o.z = acc[m][2] + 5.0f * bv.z;
        o.w = acc[m][3] + 5.0f * bv.w;
        out4[(size_t)row * 16 + cg] = o;
    }
#undef ISSUE_LOADS
#undef STORE_STAGE
}

// ---------------------------------------------------------------------------
// Inputs (metadata order):
//   0: x [10000,256] f32, 1: G (unused), 2: weight [256,64] f32,
//   3: a (unused — attention branch identically zero), 4: bias [64] f32,
//   5: qq [40960] i32, 6: rows (unused)
// output: [8192,64] f32
// ---------------------------------------------------------------------------
extern "C" void kernel_launch(void* const* d_in, const int* in_sizes, int n_in,
                              void* d_out, int out_size) {
    const float* x    = (const float*)d_in[0];
    const float* w    = (const float*)d_in[2];
    const float* bias = (const float*)d_in[4];
    const int*   qq   = (const int*)d_in[5];
    float*       out  = (float*)d_out;

    fused_kernel<<<N1R / BM, 128>>>(x, qq, w, bias, out);
}

// round 6
// speedup vs baseline: 1.5009x; 1.5009x over previous
#include <cuda_runtime.h>

#define KDIM   256
#define NF     64
#define N1R    8192
#define KH     5
#define BM     32
#define BK     32
#define NSPLIT 4
#define KSLICE (KDIM / NSPLIT)   // 64

// split-K partial sums: [NSPLIT][8192][64] = 8.4 MB (allocation-free scratch)
__device__ float g_part[NSPLIT * N1R * NF];

// ---------------------------------------------------------------------------
// Kernel 1: partial[s] = (G @ x)[:, ks:ks+64] @ W[ks:ks+64, :]
// (floor(softmax/1000) == 0 identically, so e == G exactly; 5 ones per row.)
// 1024 CTAs (256 row-tiles x 4 K-splits) -> 7 CTAs/SM, 28 warps/SM: latency
// hidden by occupancy instead of in-CTA pipelining (R5's failure mode).
// 128 threads, 4x4 microtile, BM=32 x BN=64, two BK=32 chunks.
// ---------------------------------------------------------------------------
__global__ __launch_bounds__(128, 7) void gemm_part_kernel(
        const float* __restrict__ x,
        const int*   __restrict__ qq,
        const float* __restrict__ w) {
    __shared__ float sst[BK][36];      // transposed s tile [k][row], pad->conflict-free
    __shared__ float ws[BK][NF];       // w tile
    __shared__ int   qs[BM * KH];

    const int tid = threadIdx.x;
    const int r0  = blockIdx.x * BM;
    const int ks  = blockIdx.y * KSLICE;
    const int rg  = tid >> 4;          // 0..7  -> rows rg*4..rg*4+3
    const int cg  = tid & 15;          // 0..15 -> cols cg*4..cg*4+3

    for (int t = tid; t < BM * KH; t += 128) qs[t] = qq[r0 * KH + t];
    __syncthreads();

    const float4* x4 = (const float4*)x;   // x row stride = 64 float4
    const float4* w4 = (const float4*)w;   // w row stride = 16 float4

    float acc[4][4] = {};

    #pragma unroll
    for (int c = 0; c < KSLICE / BK; c++) {
        const int kc = ks + c * BK;

        // w tile [32 x 64]: 512 float4, 4 per thread
        #pragma unroll
        for (int j = 0; j < 4; j++) {
            int idx = tid + j * 128;             // 0..511
            int kk = idx >> 4, c4 = idx & 15;
            *(float4*)&ws[kk][c4 * 4] = w4[(size_t)(kc + kk) * 16 + c4];
        }

        // gather-sum s tile [32 rows x 32 k], stored transposed
        #pragma unroll
        for (int j = 0; j < 2; j++) {
            int idx = tid + j * 128;             // 0..255
            int row = idx >> 3, c4 = idx & 7;
            const float4* xp = x4 + (kc >> 2) + c4;
            const int* q = qs + row * KH;
            float4 a0 = xp[(size_t)q[0] * 64];
            float4 a1 = xp[(size_t)q[1] * 64];
            float4 a2 = xp[(size_t)q[2] * 64];
            float4 a3 = xp[(size_t)q[3] * 64];
            float4 a4 = xp[(size_t)q[4] * 64];
            sst[c4 * 4 + 0][row] = a0.x + a1.x + a2.x + a3.x + a4.x;
            sst[c4 * 4 + 1][row] = a0.y + a1.y + a2.y + a3.y + a4.y;
            sst[c4 * 4 + 2][row] = a0.z + a1.z + a2.z + a3.z + a4.z;
            sst[c4 * 4 + 3][row] = a0.w + a1.w + a2.w + a3.w + a4.w;
        }
        __syncthreads();

        #pragma unroll
        for (int kk = 0; kk < BK; kk++) {
            float4 sv = *(const float4*)&sst[kk][rg * 4];
            float4 wv = *(const float4*)&ws[kk][cg * 4];
            acc[0][0] += sv.x * wv.x; acc[0][1] += sv.x * wv.y;
            acc[0][2] += sv.x * wv.z; acc[0][3] += sv.x * wv.w;
            acc[1][0] += sv.y * wv.x; acc[1][1] += sv.y * wv.y;
            acc[1][2] += sv.y * wv.z; acc[1][3] += sv.y * wv.w;
            acc[2][0] += sv.z * wv.x; acc[2][1] += sv.z * wv.y;
            acc[2][2] += sv.z * wv.z; acc[2][3] += sv.z * wv.w;
            acc[3][0] += sv.w * wv.x; acc[3][1] += sv.w * wv.y;
            acc[3][2] += sv.w * wv.z; acc[3][3] += sv.w * wv.w;
        }
        __syncthreads();
    }

    float4* p = (float4*)(g_part + (size_t)blockIdx.y * (N1R * NF));
    #pragma unroll
    for (int m = 0; m < 4; m++) {
        int row = r0 + rg * 4 + m;
        p[(size_t)row * 16 + cg] =
            make_float4(acc[m][0], acc[m][1], acc[m][2], acc[m][3]);
    }
}

// ---------------------------------------------------------------------------
// Kernel 2: out = sum_s partial[s] + 5*bias   (L2-resident reduce, ~2 us)
// ---------------------------------------------------------------------------
#define NQUARTER (N1R * NF / 4)    // 131072 float4 per split

__global__ __launch_bounds__(256) void reduce_kernel(const float* __restrict__ bias,
                                                     float* __restrict__ out) {
    const int i = blockIdx.x * 256 + threadIdx.x;   // float4 index, 0..131071
    const float4* p = (const float4*)g_part;
    float4 a = p[i];
    float4 b = p[i + NQUARTER];
    float4 c = p[i + 2 * NQUARTER];
    float4 d = p[i + 3 * NQUARTER];
    float4 bv = ((const float4*)bias)[i & 15];
    float4 o;
    o.x = a.x + b.x + c.x + d.x + 5.0f * bv.x;
    o.y = a.y + b.y + c.y + d.y + 5.0f * bv.y;
    o.z = a.z + b.z + c.z + d.z + 5.0f * bv.z;
    o.w = a.w + b.w + c.w + d.w + 5.0f * bv.w;
    ((float4*)out)[i] = o;
}

// ---------------------------------------------------------------------------
// Inputs (metadata order):
//   0: x [10000,256] f32, 1: G (unused), 2: weight [256,64] f32,
//   3: a (unused — attention branch identically zero), 4: bias [64] f32,
//   5: qq [40960] i32, 6: rows (unused)
// output: [8192,64] f32
// ---------------------------------------------------------------------------
extern "C" void kernel_launch(void* const* d_in, const int* in_sizes, int n_in,
                              void* d_out, int out_size) {
    const float* x    = (const float*)d_in[0];
    const float* w    = (const float*)d_in[2];
    const float* bias = (const float*)d_in[4];
    const int*   qq   = (const int*)d_in[5];
    float*       out  = (float*)d_out;

    dim3 grid(N1R / BM, NSPLIT);
    gemm_part_kernel<<<grid, 128>>>(x, qq, w);
    reduce_kernel<<<NQUARTER / 256, 256>>>(bias, out);
}